// round 15
// baseline (speedup 1.0000x reference)
#include <cuda_runtime.h>
#include <cuda_fp16.h>
#include <cstdint>
#include <math.h>

// Problem constants
#define BB 4
#define NN 4096
#define CC 1024
#define HH 16
#define MM (BB*NN)   // 16384

// ---------------- scratch (device globals; no allocation) ----------------
__device__ __half g_Wh[(size_t)MM * CC];     // qkv projection result fp16
__device__ __half g_Ah[(size_t)MM * CC];     // fp16 of x, later of T
__device__ __half g_B1[(size_t)CC * CC];     // qkv_w fp16
__device__ __half g_B2[(size_t)CC * CC];     // out_w fp16
// stats: [0,BB*CC)=norm2, [BB*CC,2BB*CC)=dots, [2BB*CC,+BB*HH)=sumpi, [+1]=counter
#define STATS_FLOATS (2 * BB * CC + BB * HH + 1)
__device__ float g_stats[STATS_FLOATS];

// ---------------- PTX helpers ---------------------------------------------
__device__ __forceinline__ uint32_t smem_u32(const void* p) {
    uint32_t a;
    asm("{ .reg .u64 t; cvta.to.shared.u64 t, %1; cvt.u32.u64 %0, t; }" : "=r"(a) : "l"(p));
    return a;
}
#define CP_ASYNC16(dst, src) \
    asm volatile("cp.async.cg.shared.global [%0], [%1], 16;" :: "r"(dst), "l"(src) : "memory")
#define CP_COMMIT() asm volatile("cp.async.commit_group;" ::: "memory")
#define CP_WAIT2()  asm volatile("cp.async.wait_group 2;" ::: "memory")

__device__ __forceinline__ void ldsm4(uint32_t* r, uint32_t addr) {
    asm volatile("ldmatrix.sync.aligned.m8n8.x4.shared.b16 {%0,%1,%2,%3}, [%4];"
        : "=r"(r[0]), "=r"(r[1]), "=r"(r[2]), "=r"(r[3]) : "r"(addr));
}
__device__ __forceinline__ void mma16816(float* c, const uint32_t* a, const uint32_t* b) {
    asm volatile("mma.sync.aligned.m16n8k16.row.col.f32.f16.f16.f32 "
        "{%0,%1,%2,%3}, {%4,%5,%6,%7}, {%8,%9}, {%0,%1,%2,%3};"
        : "+f"(c[0]), "+f"(c[1]), "+f"(c[2]), "+f"(c[3])
        : "r"(a[0]), "r"(a[1]), "r"(a[2]), "r"(a[3]), "r"(b[0]), "r"(b[1]));
}

// smem tile: 128 rows x 32 fp16 (64B/row). Swizzle 16B chunks by ((row>>1)&3)<<4.
__device__ __forceinline__ uint32_t tswz(int row, int kb) {
    return (uint32_t)(row * 64 + (kb ^ (((row >> 1) & 3) << 4)));
}

// ---------------- fp16 HMMA GEMM: C[m,n] = sum_k A[m,k]*B[n,k] (+bias) ----
// Tile 128x128, BK=32, 256 threads (warps 2m x 4n, 64x32 each), 4-stage pipe.
// 2 CTAs/SM (regs capped at 128, 64KB smem per CTA). UNCHANGED from R14.
#define STG_BYTES 16384     // 2 sub-tiles x 8KB per stage
#define OFF_A  0
#define OFF_B  8192
#define NSTG 4

__global__ __launch_bounds__(256, 2) void gemm_fp16(
    const __half* __restrict__ A, const __half* __restrict__ B,
    const float* __restrict__ bias, float* __restrict__ Cf,
    __half* __restrict__ Ch, float* __restrict__ norm2,
    int M, int N, int K)
{
    extern __shared__ __align__(1024) char smem[];
    const uint32_t sm_base = smem_u32(smem);

    const int tid  = threadIdx.x;
    const int lane = tid & 31;
    const int wid  = tid >> 5;
    const int mw   = wid >> 2;        // 0..1
    const int nw   = wid & 3;         // 0..3
    const int m0   = blockIdx.y * 128;
    const int n0   = blockIdx.x * 128;

    const int lrow = tid >> 2;        // 0..63
    const int lk16 = tid & 3;         // 0..3
    const uint32_t dst_off0 = tswz(lrow,      lk16 * 16);
    const uint32_t dst_off1 = tswz(lrow + 64, lk16 * 16);
    const char* srcA0 = (const char*)(A + (size_t)(m0 + lrow)      * K) + lk16 * 16;
    const char* srcA1 = (const char*)(A + (size_t)(m0 + lrow + 64) * K) + lk16 * 16;
    const char* srcB0 = (const char*)(B + (size_t)(n0 + lrow)      * K) + lk16 * 16;
    const char* srcB1 = (const char*)(B + (size_t)(n0 + lrow + 64) * K) + lk16 * 16;

    const int NCHUNK = K / 32;        // 32

    auto load_stage = [&](int s) {
        const uint32_t sb = sm_base + (uint32_t)(s & (NSTG - 1)) * STG_BYTES;
        const int kb = s * 64;
        CP_ASYNC16(sb + OFF_A + dst_off0, srcA0 + kb);
        CP_ASYNC16(sb + OFF_A + dst_off1, srcA1 + kb);
        CP_ASYNC16(sb + OFF_B + dst_off0, srcB0 + kb);
        CP_ASYNC16(sb + OFF_B + dst_off1, srcB1 + kb);
        CP_COMMIT();
    };

    uint32_t a_row_off[4];
    #pragma unroll
    for (int mi = 0; mi < 4; mi++) {
        int row = mw * 64 + mi * 16 + (lane & 15);
        a_row_off[mi] = (uint32_t)(row * 64);
        a_row_off[mi] |= ((uint32_t)(((row >> 1) & 3) << 4)) << 16;
    }
    const uint32_t a_kb_lane = (uint32_t)((lane >> 4) << 4);
    uint32_t b_row_off[2];
    #pragma unroll
    for (int g = 0; g < 2; g++) {
        int row = nw * 32 + g * 16 + (lane & 7) + ((lane >> 4) << 3);
        b_row_off[g] = (uint32_t)(row * 64);
        b_row_off[g] |= ((uint32_t)(((row >> 1) & 3) << 4)) << 16;
    }
    const uint32_t b_kb_lane = (uint32_t)((lane & 8) << 1);

    float acc[4][4][4];
    #pragma unroll
    for (int i = 0; i < 4; i++)
        #pragma unroll
        for (int j = 0; j < 4; j++)
            #pragma unroll
            for (int q = 0; q < 4; q++) acc[i][j][q] = 0.f;

    load_stage(0);
    load_stage(1);
    load_stage(2);

    for (int s = 0; s < NCHUNK; s++) {
        CP_WAIT2();
        __syncthreads();
        const uint32_t sb = sm_base + (uint32_t)(s & (NSTG - 1)) * STG_BYTES;

        #pragma unroll
        for (int ks = 0; ks < 2; ks++) {
            const uint32_t akb = (uint32_t)(ks * 32) + a_kb_lane;
            const uint32_t bkb = (uint32_t)(ks * 32) + b_kb_lane;
            uint32_t fA[4][4], fB[2][4];
            #pragma unroll
            for (int mi = 0; mi < 4; mi++) {
                uint32_t ro = a_row_off[mi] & 0xFFFFu;
                uint32_t sw = a_row_off[mi] >> 16;
                ldsm4(fA[mi], sb + OFF_A + ro + (akb ^ sw));
            }
            #pragma unroll
            for (int g = 0; g < 2; g++) {
                uint32_t ro = b_row_off[g] & 0xFFFFu;
                uint32_t sw = b_row_off[g] >> 16;
                ldsm4(fB[g], sb + OFF_B + ro + (bkb ^ sw));
            }
            #pragma unroll
            for (int mi = 0; mi < 4; mi++) {
                #pragma unroll
                for (int nj = 0; nj < 4; nj++) {
                    mma16816(acc[mi][nj], fA[mi], &fB[nj >> 1][(nj & 1) * 2]);
                }
            }
        }
        if (s + 3 < NCHUNK) load_stage(s + 3);
        else CP_COMMIT();
    }

    const int mbase = m0 + mw * 64 + (lane >> 2);
    const int nbase = n0 + nw * 32 + 2 * (lane & 3);
    if (Ch) {
        #pragma unroll
        for (int mi = 0; mi < 4; mi++) {
            #pragma unroll
            for (int nj = 0; nj < 4; nj++) {
                const int r0 = mbase + mi * 16;
                const int cc = nbase + nj * 8;
                __half2 v0 = __floats2half2_rn(acc[mi][nj][0], acc[mi][nj][1]);
                __half2 v1 = __floats2half2_rn(acc[mi][nj][2], acc[mi][nj][3]);
                *reinterpret_cast<__half2*>(Ch + (size_t)r0 * N + cc)       = v0;
                *reinterpret_cast<__half2*>(Ch + (size_t)(r0 + 8) * N + cc) = v1;
            }
        }
    } else {
        #pragma unroll
        for (int mi = 0; mi < 4; mi++) {
            #pragma unroll
            for (int nj = 0; nj < 4; nj++) {
                const int r0 = mbase + mi * 16;
                const int cc = nbase + nj * 8;
                float b0 = 0.f, b1 = 0.f;
                if (bias) { b0 = __ldg(bias + cc); b1 = __ldg(bias + cc + 1); }
                float2 v0 = make_float2(acc[mi][nj][0] + b0, acc[mi][nj][1] + b1);
                float2 v1 = make_float2(acc[mi][nj][2] + b0, acc[mi][nj][3] + b1);
                *reinterpret_cast<float2*>(Cf + (size_t)r0 * N + cc)       = v0;
                *reinterpret_cast<float2*>(Cf + (size_t)(r0 + 8) * N + cc) = v1;
            }
        }
    }

    if (norm2) {
        const int b = m0 >> 12;
        float cs[4][2];
        #pragma unroll
        for (int nj = 0; nj < 4; nj++) {
            cs[nj][0] = 0.f; cs[nj][1] = 0.f;
            #pragma unroll
            for (int mi = 0; mi < 4; mi++) {
                cs[nj][0] = fmaf(acc[mi][nj][0], acc[mi][nj][0], cs[nj][0]);
                cs[nj][0] = fmaf(acc[mi][nj][2], acc[mi][nj][2], cs[nj][0]);
                cs[nj][1] = fmaf(acc[mi][nj][1], acc[mi][nj][1], cs[nj][1]);
                cs[nj][1] = fmaf(acc[mi][nj][3], acc[mi][nj][3], cs[nj][1]);
            }
        }
        #pragma unroll
        for (int nj = 0; nj < 4; nj++) {
            #pragma unroll
            for (int t = 0; t < 2; t++) {
                float v = cs[nj][t];
                v += __shfl_xor_sync(0xffffffffu, v, 4);
                v += __shfl_xor_sync(0xffffffffu, v, 8);
                v += __shfl_xor_sync(0xffffffffu, v, 16);
                cs[nj][t] = v;
            }
        }
        if (lane < 4) {
            const int cb = n0 + nw * 32 + 2 * lane;
            #pragma unroll
            for (int nj = 0; nj < 4; nj++) {
                atomicAdd(&norm2[b * CC + cb + nj * 8],     cs[nj][0]);
                atomicAdd(&norm2[b * CC + cb + nj * 8 + 1], cs[nj][1]);
            }
        }
    }
}

// ---------------- fused fp32 -> fp16 cast of x, qkv_w, out_w ---------------
__global__ __launch_bounds__(256) void cast3_kernel(
    const float* __restrict__ x, const float* __restrict__ w1,
    const float* __restrict__ w2, __half* __restrict__ Ah,
    __half* __restrict__ B1, __half* __restrict__ B2,
    int n4_big, int n4_small)
{
    int i = blockIdx.x * 256 + threadIdx.x;
    const float* src; __half* dst;
    if (i < n4_big)                { src = x;  dst = Ah; }
    else if (i < n4_big + n4_small){ src = w1; dst = B1; i -= n4_big; }
    else                           { src = w2; dst = B2; i -= n4_big + n4_small; }
    float4 v = reinterpret_cast<const float4*>(src)[i];
    __half2 h[2];
    h[0] = __halves2half2(__float2half_rn(v.x), __float2half_rn(v.y));
    h[1] = __halves2half2(__float2half_rn(v.z), __float2half_rn(v.w));
    reinterpret_cast<uint2*>(dst)[i] = *reinterpret_cast<uint2*>(h);
}

// ---------------- fused pi + gate: warp-per-token + device-wide barrier ----
// 256 blocks x 256 threads, each block owns 64 tokens exclusively. Phase 1:
// softmax pi (kept in smem), accumulate dots/sumpi -> global atomics. Then
// threadfence + arrival counter + spin (all 256 blocks resident: <=128 regs
// -> >=2 blocks/SM -> 296 slots). Phase 2: apply gate to own tokens, Wh
// re-read hits L2; write fp16 T.
__global__ __launch_bounds__(256, 2) void pi_gate_kernel(
    const __half* __restrict__ Wh, const float* __restrict__ norm2,
    const float* __restrict__ temp, float* __restrict__ dots,
    float* __restrict__ sumpi, int* __restrict__ counter,
    __half* __restrict__ Th)
{
    __shared__ float sdots[CC];
    __shared__ float spi[64][HH];
    const int tid   = threadIdx.x;
    const int lane  = tid & 31;
    const int w     = tid >> 5;
    const int oct   = lane >> 3;
    const int batch = blockIdx.x >> 6;          // 64 blocks per batch
    const int tokb  = (blockIdx.x & 63) * 64;   // 64 tokens per block

    #pragma unroll
    for (int k = 0; k < 4; k++) sdots[tid * 4 + k] = 0.f;

    float inv2[4][8];
    float tmult[4];
    #pragma unroll
    for (int i = 0; i < 4; i++) {
        const float* np = norm2 + batch * CC + (i * 32 + lane) * 8;
        float4 v0 = *reinterpret_cast<const float4*>(np);
        float4 v1 = *reinterpret_cast<const float4*>(np + 4);
        float vv[8] = {v0.x, v0.y, v0.z, v0.w, v1.x, v1.y, v1.z, v1.w};
        #pragma unroll
        for (int j = 0; j < 8; j++) {
            float inv = 1.0f / fmaxf(sqrtf(vv[j]), 1e-12f);
            inv2[i][j] = inv * inv;
        }
        tmult[i] = __ldg(temp + i * 4 + oct);
    }
    __syncthreads();

    float accD[4][8];
    #pragma unroll
    for (int i = 0; i < 4; i++)
        #pragma unroll
        for (int j = 0; j < 8; j++) accD[i][j] = 0.f;
    float sumPiLoc[4] = {0.f, 0.f, 0.f, 0.f};

    for (int t = 0; t < 8; t++) {
        const size_t m = (size_t)batch * NN + tokb + w * 8 + t;
        const uint4* row = reinterpret_cast<const uint4*>(Wh + m * CC);
        float sq[4][8];
        float s[4];
        #pragma unroll
        for (int i = 0; i < 4; i++) {
            uint4 raw = row[i * 32 + lane];
            float2 f0 = __half22float2(*reinterpret_cast<__half2*>(&raw.x));
            float2 f1 = __half22float2(*reinterpret_cast<__half2*>(&raw.y));
            float2 f2 = __half22float2(*reinterpret_cast<__half2*>(&raw.z));
            float2 f3 = __half22float2(*reinterpret_cast<__half2*>(&raw.w));
            float f[8] = {f0.x, f0.y, f1.x, f1.y, f2.x, f2.y, f3.x, f3.y};
            float part = 0.f;
            #pragma unroll
            for (int j = 0; j < 8; j++) {
                sq[i][j] = f[j] * f[j];
                part = fmaf(sq[i][j], inv2[i][j], part);
            }
            part += __shfl_xor_sync(0xffffffffu, part, 1);
            part += __shfl_xor_sync(0xffffffffu, part, 2);
            part += __shfl_xor_sync(0xffffffffu, part, 4);
            s[i] = part * tmult[i];
        }
        float mx = fmaxf(fmaxf(s[0], s[1]), fmaxf(s[2], s[3]));
        mx = fmaxf(mx, __shfl_xor_sync(0xffffffffu, mx, 8));
        mx = fmaxf(mx, __shfl_xor_sync(0xffffffffu, mx, 16));
        float e[4];
        float loc = 0.f;
        #pragma unroll
        for (int i = 0; i < 4; i++) { e[i] = expf(s[i] - mx); loc += e[i]; }
        loc += __shfl_xor_sync(0xffffffffu, loc, 8);
        loc += __shfl_xor_sync(0xffffffffu, loc, 16);
        const float rinv = 1.0f / loc;
        #pragma unroll
        for (int i = 0; i < 4; i++) {
            const float p = e[i] * rinv;
            if ((lane & 7) == 0) spi[w * 8 + t][i * 4 + oct] = p;
            sumPiLoc[i] += p;
            #pragma unroll
            for (int j = 0; j < 8; j++)
                accD[i][j] = fmaf(p, sq[i][j], accD[i][j]);
        }
    }

    // flush dots/sumpi
    #pragma unroll
    for (int i = 0; i < 4; i++)
        #pragma unroll
        for (int j = 0; j < 8; j++)
            atomicAdd(&sdots[(i * 32 + lane) * 8 + j], accD[i][j]);
    __syncthreads();
    #pragma unroll
    for (int k = 0; k < 4; k++)
        atomicAdd(&dots[batch * CC + tid * 4 + k], sdots[tid * 4 + k]);
    if ((lane & 7) == 0) {
        #pragma unroll
        for (int i = 0; i < 4; i++)
            atomicAdd(&sumpi[batch * HH + i * 4 + oct], sumPiLoc[i]);
    }

    // ---- device-wide barrier ----------------------------------------------
    __threadfence();
    __syncthreads();
    if (tid == 0) {
        atomicAdd(counter, 1);
        while (*(volatile int*)counter < (int)gridDim.x) { }
    }
    __syncthreads();

    // ---- phase 2: gate ----------------------------------------------------
    float attnf[4][8];
    #pragma unroll
    for (int i = 0; i < 4; i++) {
        const float* dp = dots + batch * CC + (i * 32 + lane) * 8;
        const float spv = __ldcg(sumpi + batch * HH + i * 4 + oct) + 1e-8f;
        #pragma unroll
        for (int j = 0; j < 8; j++)
            attnf[i][j] = 1.0f / (1.0f + __ldcg(dp + j) / spv);
    }

    for (int t = 0; t < 8; t++) {
        const size_t m = (size_t)batch * NN + tokb + w * 8 + t;
        const uint4* rowW = reinterpret_cast<const uint4*>(Wh + m * CC);
        uint4* rowT = reinterpret_cast<uint4*>(Th + m * CC);
        #pragma unroll
        for (int i = 0; i < 4; i++) {
            const float p = -spi[w * 8 + t][i * 4 + oct];
            uint4 raw = rowW[i * 32 + lane];
            float2 f0 = __half22float2(*reinterpret_cast<__half2*>(&raw.x));
            float2 f1 = __half22float2(*reinterpret_cast<__half2*>(&raw.y));
            float2 f2 = __half22float2(*reinterpret_cast<__half2*>(&raw.z));
            float2 f3 = __half22float2(*reinterpret_cast<__half2*>(&raw.w));
            __half2 o0 = __floats2half2_rn(f0.x * p * attnf[i][0], f0.y * p * attnf[i][1]);
            __half2 o1 = __floats2half2_rn(f1.x * p * attnf[i][2], f1.y * p * attnf[i][3]);
            __half2 o2 = __floats2half2_rn(f2.x * p * attnf[i][4], f2.y * p * attnf[i][5]);
            __half2 o3 = __floats2half2_rn(f3.x * p * attnf[i][6], f3.y * p * attnf[i][7]);
            uint4 out;
            out.x = *reinterpret_cast<uint32_t*>(&o0);
            out.y = *reinterpret_cast<uint32_t*>(&o1);
            out.z = *reinterpret_cast<uint32_t*>(&o2);
            out.w = *reinterpret_cast<uint32_t*>(&o3);
            rowT[i * 32 + lane] = out;
        }
    }
}

// ---------------- launch ---------------------------------------------------
extern "C" void kernel_launch(void* const* d_in, const int* in_sizes, int n_in,
                              void* d_out, int out_size)
{
    const float* x     = (const float*)d_in[0];
    const float* qkv_w = (const float*)d_in[1];
    const float* temp  = (const float*)d_in[2];
    const float* out_w = (const float*)d_in[3];
    const float* out_b = (const float*)d_in[4];
    float* y = (float*)d_out;

    float *stats;
    __half *Wh, *Ah, *B1, *B2;
    cudaGetSymbolAddress((void**)&Wh,    g_Wh);
    cudaGetSymbolAddress((void**)&stats, g_stats);
    cudaGetSymbolAddress((void**)&Ah,    g_Ah);
    cudaGetSymbolAddress((void**)&B1,    g_B1);
    cudaGetSymbolAddress((void**)&B2,    g_B2);
    float* nrm  = stats;
    float* dots = stats + BB * CC;
    float* sp   = stats + 2 * BB * CC;
    int*   cnt  = (int*)(stats + 2 * BB * CC + BB * HH);

    cudaFuncSetAttribute(gemm_fp16, cudaFuncAttributeMaxDynamicSharedMemorySize, NSTG * STG_BYTES);

    cudaMemsetAsync(stats, 0, STATS_FLOATS * sizeof(float));

    const int n4_big   = (MM * CC) / 4;
    const int n4_small = (CC * CC) / 4;

    cast3_kernel<<<(n4_big + 2 * n4_small) / 256, 256>>>(
        x, qkv_w, out_w, Ah, B1, B2, n4_big, n4_small);

    dim3 ggrid(CC / 128, MM / 128);   // (8, 128)

    // 1) W = x @ qkv_w^T (fp16 HMMA) -> fp16 W + fused norm2
    gemm_fp16<<<ggrid, 256, NSTG * STG_BYTES>>>(Ah, B1, nullptr, nullptr, Wh, nrm, MM, CC, CC);
    // 2) fused pi + gate (device-wide barrier inside) -> fp16 T (reuses Ah)
    pi_gate_kernel<<<256, 256>>>(Wh, nrm, temp, dots, sp, cnt, Ah);
    // 3) y = T @ out_w^T + out_b (fp32 out)
    gemm_fp16<<<ggrid, 256, NSTG * STG_BYTES>>>(Ah, B2, out_b, y, nullptr, nullptr, MM, CC, CC);
}

// round 17
// speedup vs baseline: 1.0398x; 1.0398x over previous
#include <cuda_runtime.h>
#include <cuda_fp16.h>
#include <cstdint>
#include <math.h>

// Problem constants
#define BB 4
#define NN 4096
#define CC 1024
#define HH 16
#define MM (BB*NN)   // 16384

// ---------------- scratch (device globals; no allocation) ----------------
__device__ __half g_Wh[(size_t)MM * CC];     // qkv projection result fp16
__device__ __half g_Ah[(size_t)MM * CC];     // fp16 of x, later of T
__device__ __half g_B1[(size_t)CC * CC];     // qkv_w fp16
__device__ __half g_B2[(size_t)CC * CC];     // out_w fp16
__device__ float g_pi[(size_t)MM * HH];
// stats: [0,BB*CC) = norm2, [BB*CC,2*BB*CC) = dots, [2*BB*CC,+BB*HH) = sumpi
__device__ float g_stats[2 * BB * CC + BB * HH];

// ---------------- PTX helpers ---------------------------------------------
__device__ __forceinline__ uint32_t smem_u32(const void* p) {
    uint32_t a;
    asm("{ .reg .u64 t; cvta.to.shared.u64 t, %1; cvt.u32.u64 %0, t; }" : "=r"(a) : "l"(p));
    return a;
}
#define CP_ASYNC16(dst, src) \
    asm volatile("cp.async.cg.shared.global [%0], [%1], 16;" :: "r"(dst), "l"(src) : "memory")
#define CP_COMMIT() asm volatile("cp.async.commit_group;" ::: "memory")
#define CP_WAIT2()  asm volatile("cp.async.wait_group 2;" ::: "memory")

__device__ __forceinline__ void ldsm4(uint32_t* r, uint32_t addr) {
    asm volatile("ldmatrix.sync.aligned.m8n8.x4.shared.b16 {%0,%1,%2,%3}, [%4];"
        : "=r"(r[0]), "=r"(r[1]), "=r"(r[2]), "=r"(r[3]) : "r"(addr));
}
__device__ __forceinline__ void mma16816(float* c, const uint32_t* a, const uint32_t* b) {
    asm volatile("mma.sync.aligned.m16n8k16.row.col.f32.f16.f16.f32 "
        "{%0,%1,%2,%3}, {%4,%5,%6,%7}, {%8,%9}, {%0,%1,%2,%3};"
        : "+f"(c[0]), "+f"(c[1]), "+f"(c[2]), "+f"(c[3])
        : "r"(a[0]), "r"(a[1]), "r"(a[2]), "r"(a[3]), "r"(b[0]), "r"(b[1]));
}

// smem tile: 128 rows x 32 fp16 (64B/row). Swizzle 16B chunks by ((row>>1)&3)<<4.
__device__ __forceinline__ uint32_t tswz(int row, int kb) {
    return (uint32_t)(row * 64 + (kb ^ (((row >> 1) & 3) << 4)));
}

// ---------------- fp16 HMMA GEMM: C[m,n] = sum_k A[m,k]*B[n,k] (+bias) ----
// Tile 128x128, BK=32, 256 threads (warps 2m x 4n, 64x32 each), 4-stage pipe.
// 2 CTAs/SM (regs capped at 128, 64KB smem per CTA). FROZEN since R8.
#define STG_BYTES 16384     // 2 sub-tiles x 8KB per stage
#define OFF_A  0
#define OFF_B  8192
#define NSTG 4

__global__ __launch_bounds__(256, 2) void gemm_fp16(
    const __half* __restrict__ A, const __half* __restrict__ B,
    const float* __restrict__ bias, float* __restrict__ Cf,
    __half* __restrict__ Ch, float* __restrict__ norm2,
    int M, int N, int K)
{
    extern __shared__ __align__(1024) char smem[];
    const uint32_t sm_base = smem_u32(smem);

    const int tid  = threadIdx.x;
    const int lane = tid & 31;
    const int wid  = tid >> 5;
    const int mw   = wid >> 2;        // 0..1
    const int nw   = wid & 3;         // 0..3
    const int m0   = blockIdx.y * 128;
    const int n0   = blockIdx.x * 128;

    const int lrow = tid >> 2;        // 0..63
    const int lk16 = tid & 3;         // 0..3
    const uint32_t dst_off0 = tswz(lrow,      lk16 * 16);
    const uint32_t dst_off1 = tswz(lrow + 64, lk16 * 16);
    const char* srcA0 = (const char*)(A + (size_t)(m0 + lrow)      * K) + lk16 * 16;
    const char* srcA1 = (const char*)(A + (size_t)(m0 + lrow + 64) * K) + lk16 * 16;
    const char* srcB0 = (const char*)(B + (size_t)(n0 + lrow)      * K) + lk16 * 16;
    const char* srcB1 = (const char*)(B + (size_t)(n0 + lrow + 64) * K) + lk16 * 16;

    const int NCHUNK = K / 32;        // 32

    auto load_stage = [&](int s) {
        const uint32_t sb = sm_base + (uint32_t)(s & (NSTG - 1)) * STG_BYTES;
        const int kb = s * 64;
        CP_ASYNC16(sb + OFF_A + dst_off0, srcA0 + kb);
        CP_ASYNC16(sb + OFF_A + dst_off1, srcA1 + kb);
        CP_ASYNC16(sb + OFF_B + dst_off0, srcB0 + kb);
        CP_ASYNC16(sb + OFF_B + dst_off1, srcB1 + kb);
        CP_COMMIT();
    };

    uint32_t a_row_off[4];
    #pragma unroll
    for (int mi = 0; mi < 4; mi++) {
        int row = mw * 64 + mi * 16 + (lane & 15);
        a_row_off[mi] = (uint32_t)(row * 64);
        a_row_off[mi] |= ((uint32_t)(((row >> 1) & 3) << 4)) << 16;
    }
    const uint32_t a_kb_lane = (uint32_t)((lane >> 4) << 4);
    uint32_t b_row_off[2];
    #pragma unroll
    for (int g = 0; g < 2; g++) {
        int row = nw * 32 + g * 16 + (lane & 7) + ((lane >> 4) << 3);
        b_row_off[g] = (uint32_t)(row * 64);
        b_row_off[g] |= ((uint32_t)(((row >> 1) & 3) << 4)) << 16;
    }
    const uint32_t b_kb_lane = (uint32_t)((lane & 8) << 1);

    float acc[4][4][4];
    #pragma unroll
    for (int i = 0; i < 4; i++)
        #pragma unroll
        for (int j = 0; j < 4; j++)
            #pragma unroll
            for (int q = 0; q < 4; q++) acc[i][j][q] = 0.f;

    load_stage(0);
    load_stage(1);
    load_stage(2);

    for (int s = 0; s < NCHUNK; s++) {
        CP_WAIT2();
        __syncthreads();
        const uint32_t sb = sm_base + (uint32_t)(s & (NSTG - 1)) * STG_BYTES;

        #pragma unroll
        for (int ks = 0; ks < 2; ks++) {
            const uint32_t akb = (uint32_t)(ks * 32) + a_kb_lane;
            const uint32_t bkb = (uint32_t)(ks * 32) + b_kb_lane;
            uint32_t fA[4][4], fB[2][4];
            #pragma unroll
            for (int mi = 0; mi < 4; mi++) {
                uint32_t ro = a_row_off[mi] & 0xFFFFu;
                uint32_t sw = a_row_off[mi] >> 16;
                ldsm4(fA[mi], sb + OFF_A + ro + (akb ^ sw));
            }
            #pragma unroll
            for (int g = 0; g < 2; g++) {
                uint32_t ro = b_row_off[g] & 0xFFFFu;
                uint32_t sw = b_row_off[g] >> 16;
                ldsm4(fB[g], sb + OFF_B + ro + (bkb ^ sw));
            }
            #pragma unroll
            for (int mi = 0; mi < 4; mi++) {
                #pragma unroll
                for (int nj = 0; nj < 4; nj++) {
                    mma16816(acc[mi][nj], fA[mi], &fB[nj >> 1][(nj & 1) * 2]);
                }
            }
        }
        if (s + 3 < NCHUNK) load_stage(s + 3);
        else CP_COMMIT();
    }

    const int mbase = m0 + mw * 64 + (lane >> 2);
    const int nbase = n0 + nw * 32 + 2 * (lane & 3);
    if (Ch) {
        #pragma unroll
        for (int mi = 0; mi < 4; mi++) {
            #pragma unroll
            for (int nj = 0; nj < 4; nj++) {
                const int r0 = mbase + mi * 16;
                const int cc = nbase + nj * 8;
                __half2 v0 = __floats2half2_rn(acc[mi][nj][0], acc[mi][nj][1]);
                __half2 v1 = __floats2half2_rn(acc[mi][nj][2], acc[mi][nj][3]);
                *reinterpret_cast<__half2*>(Ch + (size_t)r0 * N + cc)       = v0;
                *reinterpret_cast<__half2*>(Ch + (size_t)(r0 + 8) * N + cc) = v1;
            }
        }
    } else {
        #pragma unroll
        for (int mi = 0; mi < 4; mi++) {
            #pragma unroll
            for (int nj = 0; nj < 4; nj++) {
                const int r0 = mbase + mi * 16;
                const int cc = nbase + nj * 8;
                float b0 = 0.f, b1 = 0.f;
                if (bias) { b0 = __ldg(bias + cc); b1 = __ldg(bias + cc + 1); }
                float2 v0 = make_float2(acc[mi][nj][0] + b0, acc[mi][nj][1] + b1);
                float2 v1 = make_float2(acc[mi][nj][2] + b0, acc[mi][nj][3] + b1);
                *reinterpret_cast<float2*>(Cf + (size_t)r0 * N + cc)       = v0;
                *reinterpret_cast<float2*>(Cf + (size_t)(r0 + 8) * N + cc) = v1;
            }
        }
    }

    if (norm2) {
        const int b = m0 >> 12;
        float cs[4][2];
        #pragma unroll
        for (int nj = 0; nj < 4; nj++) {
            cs[nj][0] = 0.f; cs[nj][1] = 0.f;
            #pragma unroll
            for (int mi = 0; mi < 4; mi++) {
                cs[nj][0] = fmaf(acc[mi][nj][0], acc[mi][nj][0], cs[nj][0]);
                cs[nj][0] = fmaf(acc[mi][nj][2], acc[mi][nj][2], cs[nj][0]);
                cs[nj][1] = fmaf(acc[mi][nj][1], acc[mi][nj][1], cs[nj][1]);
                cs[nj][1] = fmaf(acc[mi][nj][3], acc[mi][nj][3], cs[nj][1]);
            }
        }
        #pragma unroll
        for (int nj = 0; nj < 4; nj++) {
            #pragma unroll
            for (int t = 0; t < 2; t++) {
                float v = cs[nj][t];
                v += __shfl_xor_sync(0xffffffffu, v, 4);
                v += __shfl_xor_sync(0xffffffffu, v, 8);
                v += __shfl_xor_sync(0xffffffffu, v, 16);
                cs[nj][t] = v;
            }
        }
        if (lane < 4) {
            const int cb = n0 + nw * 32 + 2 * lane;
            #pragma unroll
            for (int nj = 0; nj < 4; nj++) {
                atomicAdd(&norm2[b * CC + cb + nj * 8],     cs[nj][0]);
                atomicAdd(&norm2[b * CC + cb + nj * 8 + 1], cs[nj][1]);
            }
        }
    }
}

// ---------------- fused fp32 -> fp16 cast of x, qkv_w, out_w ---------------
__global__ __launch_bounds__(256) void cast3_kernel(
    const float* __restrict__ x, const float* __restrict__ w1,
    const float* __restrict__ w2, __half* __restrict__ Ah,
    __half* __restrict__ B1, __half* __restrict__ B2,
    int n4_big, int n4_small)
{
    int i = blockIdx.x * 256 + threadIdx.x;
    const float* src; __half* dst;
    if (i < n4_big)                { src = x;  dst = Ah; }
    else if (i < n4_big + n4_small){ src = w1; dst = B1; i -= n4_big; }
    else                           { src = w2; dst = B2; i -= n4_big + n4_small; }
    float4 v = reinterpret_cast<const float4*>(src)[i];
    __half2 h[2];
    h[0] = __halves2half2(__float2half_rn(v.x), __float2half_rn(v.y));
    h[1] = __halves2half2(__float2half_rn(v.z), __float2half_rn(v.w));
    reinterpret_cast<uint2*>(dst)[i] = *reinterpret_cast<uint2*>(h);
}

// ---------------- pi + reductions: warp-per-token (R14 proven) -------------
__global__ __launch_bounds__(256) void pi_kernel(
    const __half* __restrict__ Wh, const float* __restrict__ norm2,
    const float* __restrict__ temp,
    float* __restrict__ pi_out, float* __restrict__ dots,
    float* __restrict__ sumpi)
{
    __shared__ float sdots[CC];
    const int tid   = threadIdx.x;
    const int lane  = tid & 31;
    const int w     = tid >> 5;
    const int oct   = lane >> 3;
    const int batch = blockIdx.x >> 6;          // 64 blocks per batch
    const int tokb  = (blockIdx.x & 63) * 64;   // 64 tokens per block

    #pragma unroll
    for (int k = 0; k < 4; k++) sdots[tid * 4 + k] = 0.f;

    float inv2[4][8];
    float tmult[4];
    #pragma unroll
    for (int i = 0; i < 4; i++) {
        const float* np = norm2 + batch * CC + (i * 32 + lane) * 8;
        float4 v0 = *reinterpret_cast<const float4*>(np);
        float4 v1 = *reinterpret_cast<const float4*>(np + 4);
        float vv[8] = {v0.x, v0.y, v0.z, v0.w, v1.x, v1.y, v1.z, v1.w};
        #pragma unroll
        for (int j = 0; j < 8; j++) {
            float inv = 1.0f / fmaxf(sqrtf(vv[j]), 1e-12f);
            inv2[i][j] = inv * inv;
        }
        tmult[i] = __ldg(temp + i * 4 + oct);
    }
    __syncthreads();

    float accD[4][8];
    #pragma unroll
    for (int i = 0; i < 4; i++)
        #pragma unroll
        for (int j = 0; j < 8; j++) accD[i][j] = 0.f;
    float sumPiLoc[4] = {0.f, 0.f, 0.f, 0.f};

    for (int t = 0; t < 8; t++) {
        const size_t m = (size_t)batch * NN + tokb + w * 8 + t;
        const uint4* row = reinterpret_cast<const uint4*>(Wh + m * CC);
        float sq[4][8];
        float s[4];
        #pragma unroll
        for (int i = 0; i < 4; i++) {
            uint4 raw = row[i * 32 + lane];
            float2 f0 = __half22float2(*reinterpret_cast<__half2*>(&raw.x));
            float2 f1 = __half22float2(*reinterpret_cast<__half2*>(&raw.y));
            float2 f2 = __half22float2(*reinterpret_cast<__half2*>(&raw.z));
            float2 f3 = __half22float2(*reinterpret_cast<__half2*>(&raw.w));
            float f[8] = {f0.x, f0.y, f1.x, f1.y, f2.x, f2.y, f3.x, f3.y};
            float part = 0.f;
            #pragma unroll
            for (int j = 0; j < 8; j++) {
                sq[i][j] = f[j] * f[j];
                part = fmaf(sq[i][j], inv2[i][j], part);
            }
            part += __shfl_xor_sync(0xffffffffu, part, 1);
            part += __shfl_xor_sync(0xffffffffu, part, 2);
            part += __shfl_xor_sync(0xffffffffu, part, 4);
            s[i] = part * tmult[i];
        }
        float mx = fmaxf(fmaxf(s[0], s[1]), fmaxf(s[2], s[3]));
        mx = fmaxf(mx, __shfl_xor_sync(0xffffffffu, mx, 8));
        mx = fmaxf(mx, __shfl_xor_sync(0xffffffffu, mx, 16));
        float e[4];
        float loc = 0.f;
        #pragma unroll
        for (int i = 0; i < 4; i++) { e[i] = expf(s[i] - mx); loc += e[i]; }
        loc += __shfl_xor_sync(0xffffffffu, loc, 8);
        loc += __shfl_xor_sync(0xffffffffu, loc, 16);
        const float rinv = 1.0f / loc;
        #pragma unroll
        for (int i = 0; i < 4; i++) {
            const float p = e[i] * rinv;
            if ((lane & 7) == 0) pi_out[m * HH + i * 4 + oct] = p;
            sumPiLoc[i] += p;
            #pragma unroll
            for (int j = 0; j < 8; j++)
                accD[i][j] = fmaf(p, sq[i][j], accD[i][j]);
        }
    }

    #pragma unroll
    for (int i = 0; i < 4; i++)
        #pragma unroll
        for (int j = 0; j < 8; j++)
            atomicAdd(&sdots[(i * 32 + lane) * 8 + j], accD[i][j]);
    __syncthreads();
    #pragma unroll
    for (int k = 0; k < 4; k++)
        atomicAdd(&dots[batch * CC + tid * 4 + k], sdots[tid * 4 + k]);
    if ((lane & 7) == 0) {
        #pragma unroll
        for (int i = 0; i < 4; i++)
            atomicAdd(&sumpi[batch * HH + i * 4 + oct], sumPiLoc[i]);
    }
}

// ---- gate (attn fused): T = -W * pi * (1/(1+dots/(sumpi+1e-8))) -> fp16 ---
__global__ __launch_bounds__(256) void gate_kernel(
    const __half* __restrict__ Wh, const float* __restrict__ pi,
    const float* __restrict__ dots, const float* __restrict__ sumpi,
    __half* __restrict__ Th)
{
    const size_t idx  = (size_t)blockIdx.x * 256 + threadIdx.x;
    const size_t base = idx * 4;
    const int m = (int)(base >> 10);
    const int c = (int)(base & (CC - 1));
    const int b = m >> 12;
    const int h = c >> 6;
    uint2 raw = *reinterpret_cast<const uint2*>(Wh + base);
    float2 w01 = __half22float2(*reinterpret_cast<__half2*>(&raw.x));
    float2 w23 = __half22float2(*reinterpret_cast<__half2*>(&raw.y));
    float4 d4 = *reinterpret_cast<const float4*>(dots + b * CC + c);
    const float spv = sumpi[b * HH + h] + 1e-8f;
    const float p = -pi[(size_t)m * HH + h];
    float a0 = 1.0f / (1.0f + d4.x / spv);
    float a1 = 1.0f / (1.0f + d4.y / spv);
    float a2 = 1.0f / (1.0f + d4.z / spv);
    float a3 = 1.0f / (1.0f + d4.w / spv);
    __half2 o[2];
    o[0] = __halves2half2(__float2half_rn(w01.x * p * a0),
                          __float2half_rn(w01.y * p * a1));
    o[1] = __halves2half2(__float2half_rn(w23.x * p * a2),
                          __float2half_rn(w23.y * p * a3));
    reinterpret_cast<uint2*>(Th)[idx] = *reinterpret_cast<uint2*>(o);
}

// ---------------- launch ---------------------------------------------------
extern "C" void kernel_launch(void* const* d_in, const int* in_sizes, int n_in,
                              void* d_out, int out_size)
{
    const float* x     = (const float*)d_in[0];
    const float* qkv_w = (const float*)d_in[1];
    const float* temp  = (const float*)d_in[2];
    const float* out_w = (const float*)d_in[3];
    const float* out_b = (const float*)d_in[4];
    float* y = (float*)d_out;

    float *pi, *stats;
    __half *Wh, *Ah, *B1, *B2;
    cudaGetSymbolAddress((void**)&Wh,    g_Wh);
    cudaGetSymbolAddress((void**)&pi,    g_pi);
    cudaGetSymbolAddress((void**)&stats, g_stats);
    cudaGetSymbolAddress((void**)&Ah,    g_Ah);
    cudaGetSymbolAddress((void**)&B1,    g_B1);
    cudaGetSymbolAddress((void**)&B2,    g_B2);
    float* nrm  = stats;
    float* dots = stats + BB * CC;
    float* sp   = stats + 2 * BB * CC;

    cudaFuncSetAttribute(gemm_fp16, cudaFuncAttributeMaxDynamicSharedMemorySize, NSTG * STG_BYTES);

    cudaMemsetAsync(stats, 0, (2 * BB * CC + BB * HH) * sizeof(float));

    const int n4_big   = (MM * CC) / 4;
    const int n4_small = (CC * CC) / 4;

    // single fused cast of x, qkv_w, out_w
    cast3_kernel<<<(n4_big + 2 * n4_small) / 256, 256>>>(
        x, qkv_w, out_w, Ah, B1, B2, n4_big, n4_small);

    dim3 ggrid(CC / 128, MM / 128);   // (8, 128)

    // 1) W = x @ qkv_w^T (fp16 HMMA) -> fp16 W + fused norm2
    gemm_fp16<<<ggrid, 256, NSTG * STG_BYTES>>>(Ah, B1, nullptr, nullptr, Wh, nrm, MM, CC, CC);
    // 2) stats (warp-per-token)
    pi_kernel<<<256, 256>>>(Wh, nrm, temp, pi, dots, sp);
    // 3) gate (attn fused) -> fp16 (reuses Ah)
    gate_kernel<<<(int)(((size_t)MM * CC / 4) / 256), 256>>>(Wh, pi, dots, sp, Ah);
    // 4) y = T @ out_w^T + out_b (fp32 out)
    gemm_fp16<<<ggrid, 256, NSTG * STG_BYTES>>>(Ah, B2, out_b, y, nullptr, nullptr, MM, CC, CC);
}